// round 4
// baseline (speedup 1.0000x reference)
#include <cuda_runtime.h>
#include <cuda_bf16.h>
#include <math.h>
#include <stdint.h>

#define Bc 4
#define Gc 2048
#define Dc 256
#define Hc 8
#define Lc 4
#define FFNc 1024
#define HDc 32
#define BGc (Bc*Gc)
#define NCc 32
#define Tc (Gc/NCc)   /* 64 */

// ---------------- scratch (no mallocs allowed) ----------------
__device__ float g_h[BGc*Dc];
__device__ float g_z[BGc*Dc];
__device__ float g_q[BGc*Dc];
__device__ float g_k[BGc*Dc];
__device__ float g_v[BGc*Dc];
__device__ float g_u[BGc*FFNc];
__device__ float g_cKV[Bc*Hc*NCc*HDc*HDc];
__device__ float g_cK[Bc*Hc*NCc*HDc];

// ---------------- embed ----------------
__global__ void embed_kernel(const float* __restrict__ x, const float* __restrict__ ge){
    int row = blockIdx.x;
    int d = threadIdx.x;
    int g = row % Gc;
    float xv = x[row];
    int i = (d < Dc/2) ? d : d - Dc/2;
    float invf = expf(-((2.0f*(float)i)/(float)Dc) * 4.6051701859880914f);
    float f = xv * invf;
    float ree = (d < Dc/2) ? sinf(f) : cosf(f);
    if (xv == -10.0f) ree = 0.0f;
    g_h[(size_t)row*Dc + d] = ge[(size_t)g*Dc + d] + ree;
}

// ---------------- layernorm: warp-per-row ----------------
__global__ void ln_kernel(const float* __restrict__ in, const float* __restrict__ gamma,
                          const float* __restrict__ beta, float* __restrict__ out){
    int row  = blockIdx.x*8 + (threadIdx.x >> 5);
    int lane = threadIdx.x & 31;
    const float* p = in + (size_t)row*Dc;
    float vals[8]; float s = 0.f;
    #pragma unroll
    for (int j=0;j<8;j++){ vals[j] = p[lane + j*32]; s += vals[j]; }
    #pragma unroll
    for (int o=16;o;o>>=1) s += __shfl_xor_sync(0xffffffffu, s, o);
    float mu = s * (1.0f/(float)Dc);
    float vs = 0.f;
    #pragma unroll
    for (int j=0;j<8;j++){ float dd = vals[j]-mu; vs += dd*dd; }
    #pragma unroll
    for (int o=16;o;o>>=1) vs += __shfl_xor_sync(0xffffffffu, vs, o);
    float r = rsqrtf(vs*(1.0f/(float)Dc) + 1e-5f);
    float* po = out + (size_t)row*Dc;
    #pragma unroll
    for (int j=0;j<8;j++){
        int c = lane + j*32;
        po[c] = (vals[j]-mu)*r*gamma[c] + beta[c];
    }
}

// ---------------- bf16 split-precision tensor-core GEMM ----------------
#define EPI_NONE   0
#define EPI_SQUARE 1
#define EPI_GELU   2

__device__ __forceinline__ uint16_t bfb(float x){
    __nv_bfloat16 h = __float2bfloat16(x);
    return *reinterpret_cast<uint16_t*>(&h);
}
__device__ __forceinline__ float bff(uint16_t b){
    __nv_bfloat16 h = *reinterpret_cast<__nv_bfloat16*>(&b);
    return __bfloat162float(h);
}
__device__ __forceinline__ uint32_t pack2(uint16_t lo, uint16_t hi){
    return ((uint32_t)hi<<16) | (uint32_t)lo;
}
__device__ __forceinline__ void mma16816(float* c, const uint32_t* a, const uint32_t* b){
    asm volatile("mma.sync.aligned.m16n8k16.row.col.f32.bf16.bf16.f32 "
        "{%0,%1,%2,%3}, {%4,%5,%6,%7}, {%8,%9}, {%0,%1,%2,%3};\n"
        : "+f"(c[0]),"+f"(c[1]),"+f"(c[2]),"+f"(c[3])
        : "r"(a[0]),"r"(a[1]),"r"(a[2]),"r"(a[3]), "r"(b[0]),"r"(b[1]));
}

// block tile 128x128, BK=32, 256 threads, warp tile 32x64 (warps 4x2)
#define ASTR 40      /* u16 stride for A smem (conflict-free) */
#define BSTR 136     /* u32 stride for B smem (conflict-free)  */
#define ABYTES (128*ASTR*2)
#define BBYTES (16*BSTR*4)
#define BUFB   (2*ABYTES + 2*BBYTES)
#define SMEM_TOTAL_GEMM (2*BUFB)

__device__ __forceinline__ void load_tile(int tid, int row0, int col0, int k0,
    int K, int N, const float* __restrict__ A, const float* __restrict__ Bw,
    float* a_pre, float* b_pre)
{
    #pragma unroll
    for (int i=0;i<4;i++){
        int id = tid + i*256;
        int r = id>>3, c = (id&7)*4;
        const float4 v = *(const float4*)(A + (size_t)(row0+r)*K + k0 + c);
        a_pre[i*4+0]=v.x; a_pre[i*4+1]=v.y; a_pre[i*4+2]=v.z; a_pre[i*4+3]=v.w;
    }
    #pragma unroll
    for (int i=0;i<8;i++){
        int id = tid + i*256;
        int k2 = id>>7, n = id&127;
        const float* p = Bw + (size_t)(k0+2*k2)*N + col0 + n;
        b_pre[2*i+0] = p[0];
        b_pre[2*i+1] = p[N];
    }
}

__device__ __forceinline__ void store_tile(int tid, const float* a_pre, const float* b_pre,
    uint16_t* Ah, uint16_t* Al, uint32_t* Bh, uint32_t* Bl)
{
    #pragma unroll
    for (int i=0;i<4;i++){
        int id = tid + i*256;
        int r = id>>3, c = (id&7)*4;
        uint16_t h[4], l[4];
        #pragma unroll
        for (int j=0;j<4;j++){
            float v = a_pre[i*4+j];
            h[j] = bfb(v);
            l[j] = bfb(v - bff(h[j]));
        }
        *(uint32_t*)&Ah[r*ASTR+c]   = pack2(h[0],h[1]);
        *(uint32_t*)&Ah[r*ASTR+c+2] = pack2(h[2],h[3]);
        *(uint32_t*)&Al[r*ASTR+c]   = pack2(l[0],l[1]);
        *(uint32_t*)&Al[r*ASTR+c+2] = pack2(l[2],l[3]);
    }
    #pragma unroll
    for (int i=0;i<8;i++){
        int id = tid + i*256;
        int k2 = id>>7, n = id&127;
        float v0 = b_pre[2*i+0], v1 = b_pre[2*i+1];
        uint16_t h0 = bfb(v0), h1 = bfb(v1);
        uint16_t l0 = bfb(v0 - bff(h0)), l1 = bfb(v1 - bff(h1));
        Bh[k2*BSTR+n] = pack2(h0,h1);
        Bl[k2*BSTR+n] = pack2(l0,l1);
    }
}

template<int EPI, bool RES, bool QKV>
__global__ void __launch_bounds__(256,1) mma_gemm(int M, int N, int K,
        const float* __restrict__ A,
        const float* W0, const float* W1, const float* W2,
        const float* b0, const float* b1, const float* b2,
        float* C0, float* C1, float* C2){
    extern __shared__ unsigned char dynsmem[];

    const int z = QKV ? blockIdx.z : 0;
    const float* Bw   = (z==0)?W0:((z==1)?W1:W2);
    const float* bias = (z==0)?b0:((z==1)?b1:b2);
    float*       C    = (z==0)?C0:((z==1)?C1:C2);

    const int tid  = threadIdx.x;
    const int row0 = blockIdx.y*128;
    const int col0 = blockIdx.x*128;
    const int w    = tid>>5;
    const int wm   = w & 3;
    const int wn   = w >> 2;
    const int lane = tid & 31;
    const int g    = lane >> 2;
    const int t4   = lane & 3;

    uint16_t* AhP[2]; uint16_t* AlP[2]; uint32_t* BhP[2]; uint32_t* BlP[2];
    #pragma unroll
    for (int bfr=0;bfr<2;bfr++){
        unsigned char* base = dynsmem + bfr*BUFB;
        AhP[bfr] = (uint16_t*)base;
        AlP[bfr] = (uint16_t*)(base + ABYTES);
        BhP[bfr] = (uint32_t*)(base + 2*ABYTES);
        BlP[bfr] = (uint32_t*)(base + 2*ABYTES + BBYTES);
    }

    float a_pre[16], b_pre[16];
    load_tile(tid,row0,col0,0,K,N,A,Bw,a_pre,b_pre);

    float acc[2][8][4];
    #pragma unroll
    for (int mt=0;mt<2;mt++)
        #pragma unroll
        for (int nt=0;nt<8;nt++)
            #pragma unroll
            for (int q=0;q<4;q++) acc[mt][nt][q]=0.f;

    store_tile(tid,a_pre,b_pre,AhP[0],AlP[0],BhP[0],BlP[0]);
    __syncthreads();

    const int nk = K/32;
    for (int kt=0; kt<nk; kt++){
        const int cur = kt & 1;
        if (kt+1 < nk)
            load_tile(tid,row0,col0,(kt+1)*32,K,N,A,Bw,a_pre,b_pre);

        const uint16_t* cAh = AhP[cur];
        const uint16_t* cAl = AlP[cur];
        const uint32_t* cBh = BhP[cur];
        const uint32_t* cBl = BlP[cur];

        #pragma unroll
        for (int ks=0;ks<2;ks++){
            uint32_t afh[2][4], afl[2][4];
            #pragma unroll
            for (int mt=0;mt<2;mt++){
                int r  = wm*32 + mt*16 + g;
                int cb = ks*16 + t4*2;
                afh[mt][0]=*(const uint32_t*)&cAh[r*ASTR+cb];
                afh[mt][1]=*(const uint32_t*)&cAh[(r+8)*ASTR+cb];
                afh[mt][2]=*(const uint32_t*)&cAh[r*ASTR+cb+8];
                afh[mt][3]=*(const uint32_t*)&cAh[(r+8)*ASTR+cb+8];
                afl[mt][0]=*(const uint32_t*)&cAl[r*ASTR+cb];
                afl[mt][1]=*(const uint32_t*)&cAl[(r+8)*ASTR+cb];
                afl[mt][2]=*(const uint32_t*)&cAl[r*ASTR+cb+8];
                afl[mt][3]=*(const uint32_t*)&cAl[(r+8)*ASTR+cb+8];
            }
            uint32_t bh_[8][2], bl_[8][2];
            #pragma unroll
            for (int nt=0;nt<8;nt++){
                int n  = wn*64 + nt*8 + g;
                int k2 = ks*8 + t4;
                bh_[nt][0]=cBh[k2*BSTR+n]; bh_[nt][1]=cBh[(k2+4)*BSTR+n];
                bl_[nt][0]=cBl[k2*BSTR+n]; bl_[nt][1]=cBl[(k2+4)*BSTR+n];
            }
            // 3 groups of 16 independent MMAs (no back-to-back same-acc deps)
            #pragma unroll
            for (int nt=0;nt<8;nt++)
                #pragma unroll
                for (int mt=0;mt<2;mt++)
                    mma16816(acc[mt][nt], afh[mt], bh_[nt]);
            #pragma unroll
            for (int nt=0;nt<8;nt++)
                #pragma unroll
                for (int mt=0;mt<2;mt++)
                    mma16816(acc[mt][nt], afh[mt], bl_[nt]);
            #pragma unroll
            for (int nt=0;nt<8;nt++)
                #pragma unroll
                for (int mt=0;mt<2;mt++)
                    mma16816(acc[mt][nt], afl[mt], bh_[nt]);
        }

        if (kt+1 < nk)
            store_tile(tid,a_pre,b_pre,AhP[cur^1],AlP[cur^1],BhP[cur^1],BlP[cur^1]);
        __syncthreads();
    }

    // epilogue
    const int epi = QKV ? ((z==2) ? EPI_NONE : EPI_SQUARE) : EPI;
    #pragma unroll
    for (int mt=0;mt<2;mt++){
        #pragma unroll
        for (int nt=0;nt<8;nt++){
            int r = row0 + wm*32 + mt*16 + g;
            int n = col0 + wn*64 + nt*8 + t4*2;
            #pragma unroll
            for (int half=0; half<2; half++){
                int rr = r + half*8;
                float v0 = acc[mt][nt][half*2+0] + bias[n];
                float v1 = acc[mt][nt][half*2+1] + bias[n+1];
                if (epi == EPI_SQUARE){ v0=v0*v0; v1=v1*v1; }
                if (epi == EPI_GELU){
                    v0 = 0.5f*v0*(1.0f + erff(v0*0.70710678118654752f));
                    v1 = 0.5f*v1*(1.0f + erff(v1*0.70710678118654752f));
                }
                size_t idx = (size_t)rr*N + n;
                if (RES){ C[idx] += v0; C[idx+1] += v1; }
                else    { C[idx]  = v0; C[idx+1]  = v1; }
            }
        }
    }
}

// ---------------- attention scan, chunked ----------------
__global__ void scanA_kernel(){
    int bid = blockIdx.x;
    int c  = bid & (NCc-1);
    int bh = bid >> 5;
    int b  = bh >> 3;
    int hh = bh & 7;
    int m = threadIdx.x & 31;
    int d = threadIdx.x >> 5;
    size_t base = ((size_t)(b*Gc + c*Tc))*Dc + hh*HDc;
    float S = 0.f, ks = 0.f;
    for (int s=0;s<Tc;s++){
        float km = g_k[base + (size_t)s*Dc + m];
        float vd = g_v[base + (size_t)s*Dc + d];
        S  += km*vd;
        ks += km;
    }
    g_cKV[(size_t)bid*1024 + threadIdx.x] = S;
    if (d == 0) g_cK[bid*32 + m] = ks;
}

// grid: 32 bh * 8 segments, 128 threads each
__global__ void scanB_kernel(){
    int bh  = blockIdx.x >> 3;
    int seg = blockIdx.x & 7;
    int t   = seg*128 + threadIdx.x;
    float run = 0.f;
    for (int c=0;c<NCc;c++){
        size_t idx = ((size_t)(bh*NCc + c))*1024 + t;
        float val = g_cKV[idx];
        g_cKV[idx] = run;
        run += val;
    }
    if (seg == 0 && threadIdx.x < 32){
        float run2 = 0.f;
        int m = threadIdx.x;
        for (int c=0;c<NCc;c++){
            int idx = (bh*NCc + c)*32 + m;
            float val = g_cK[idx];
            g_cK[idx] = run2;
            run2 += val;
        }
    }
}

__global__ void scanC_kernel(){
    int bid = blockIdx.x;
    int c  = bid & (NCc-1);
    int bh = bid >> 5;
    int b  = bh >> 3;
    int hh = bh & 7;
    int m = threadIdx.x & 31;
    int d = threadIdx.x >> 5;
    size_t base = ((size_t)(b*Gc + c*Tc))*Dc + hh*HDc;
    float S  = g_cKV[(size_t)bid*1024 + threadIdx.x];
    float ks = g_cK[bid*32 + m];
    for (int s=0;s<Tc;s++){
        float qm = g_q[base + (size_t)s*Dc + m];
        float km = g_k[base + (size_t)s*Dc + m];
        float vd = g_v[base + (size_t)s*Dc + d];
        ks += km;
        S  += km*vd;
        float num = qm*S;
        float den = qm*ks;
        #pragma unroll
        for (int o=16;o;o>>=1){
            num += __shfl_xor_sync(0xffffffffu, num, o);
            den += __shfl_xor_sync(0xffffffffu, den, o);
        }
        if (m == 0) g_h[base + (size_t)s*Dc + d] += num/(den + 1e-16f);
    }
}

// ---------------- head ----------------
__global__ void out_kernel(const float* __restrict__ Wo, const float* __restrict__ bo,
                           float* __restrict__ out){
    int row  = blockIdx.x*8 + (threadIdx.x >> 5);
    int lane = threadIdx.x & 31;
    float s = 0.f;
    #pragma unroll
    for (int j=0;j<8;j++){
        int d = lane + j*32;
        s += g_h[(size_t)row*Dc + d] * Wo[d];
    }
    #pragma unroll
    for (int o=16;o;o>>=1) s += __shfl_xor_sync(0xffffffffu, s, o);
    if (lane == 0) out[row] = s + bo[0];
}

// ---------------- launch ----------------
extern "C" void kernel_launch(void* const* d_in, const int* in_sizes, int n_in,
                              void* d_out, int out_size){
    const float* x    = (const float*)d_in[0];
    const float* ge   = (const float*)d_in[1];
    const float* Wq   = (const float*)d_in[2];
    const float* bq   = (const float*)d_in[3];
    const float* Wk   = (const float*)d_in[4];
    const float* bk   = (const float*)d_in[5];
    const float* Wv   = (const float*)d_in[6];
    const float* bv   = (const float*)d_in[7];
    const float* ln1g = (const float*)d_in[8];
    const float* ln1b = (const float*)d_in[9];
    const float* ln2g = (const float*)d_in[10];
    const float* ln2b = (const float*)d_in[11];
    const float* WU   = (const float*)d_in[12];
    const float* bU   = (const float*)d_in[13];
    const float* WV   = (const float*)d_in[14];
    const float* bV   = (const float*)d_in[15];
    const float* Wo   = (const float*)d_in[16];
    const float* bo   = (const float*)d_in[17];
    float* out = (float*)d_out;

    float *ph, *pz, *pq, *pk, *pv, *pu;
    cudaGetSymbolAddress((void**)&ph, g_h);
    cudaGetSymbolAddress((void**)&pz, g_z);
    cudaGetSymbolAddress((void**)&pq, g_q);
    cudaGetSymbolAddress((void**)&pk, g_k);
    cudaGetSymbolAddress((void**)&pv, g_v);
    cudaGetSymbolAddress((void**)&pu, g_u);

    cudaFuncSetAttribute(mma_gemm<EPI_NONE,false,true>,
        cudaFuncAttributeMaxDynamicSharedMemorySize, SMEM_TOTAL_GEMM);
    cudaFuncSetAttribute(mma_gemm<EPI_GELU,false,false>,
        cudaFuncAttributeMaxDynamicSharedMemorySize, SMEM_TOTAL_GEMM);
    cudaFuncSetAttribute(mma_gemm<EPI_NONE,true,false>,
        cudaFuncAttributeMaxDynamicSharedMemorySize, SMEM_TOTAL_GEMM);

    embed_kernel<<<BGc, Dc>>>(x, ge);

    for (int l=0;l<Lc;l++){
        ln_kernel<<<BGc/8, 256>>>(ph, ln1g + l*Dc, ln1b + l*Dc, pz);
        dim3 gqkv(Dc/128, BGc/128, 3);
        mma_gemm<EPI_NONE,false,true><<<gqkv,256,SMEM_TOTAL_GEMM>>>(BGc, Dc, Dc, pz,
            Wq + (size_t)l*Dc*Dc, Wk + (size_t)l*Dc*Dc, Wv + (size_t)l*Dc*Dc,
            bq + l*Dc, bk + l*Dc, bv + l*Dc,
            pq, pk, pv);
        scanA_kernel<<<Bc*Hc*NCc, 1024>>>();
        scanB_kernel<<<Bc*Hc*8, 128>>>();
        scanC_kernel<<<Bc*Hc*NCc, 1024>>>();

        ln_kernel<<<BGc/8, 256>>>(ph, ln2g + l*Dc, ln2b + l*Dc, pz);
        dim3 gu(FFNc/128, BGc/128, 1);
        mma_gemm<EPI_GELU,false,false><<<gu,256,SMEM_TOTAL_GEMM>>>(BGc, FFNc, Dc, pz,
            WU + (size_t)l*Dc*FFNc, WU + (size_t)l*Dc*FFNc, WU + (size_t)l*Dc*FFNc,
            bU + l*FFNc, bU + l*FFNc, bU + l*FFNc,
            pu, pu, pu);
        dim3 gv(Dc/128, BGc/128, 1);
        mma_gemm<EPI_NONE,true,false><<<gv,256,SMEM_TOTAL_GEMM>>>(BGc, Dc, FFNc, pu,
            WV + (size_t)l*FFNc*Dc, WV + (size_t)l*FFNc*Dc, WV + (size_t)l*FFNc*Dc,
            bV + l*Dc, bV + l*Dc, bV + l*Dc,
            ph, ph, ph);
    }

    out_kernel<<<BGc/8, 256>>>(Wo, bo, out);
}

// round 5
// speedup vs baseline: 1.7594x; 1.7594x over previous
#include <cuda_runtime.h>
#include <cuda_bf16.h>
#include <math.h>
#include <stdint.h>

#define Bc 4
#define Gc 2048
#define Dc 256
#define Hc 8
#define Lc 4
#define FFNc 1024
#define HDc 32
#define BGc (Bc*Gc)
#define NCc 32
#define Tc (Gc/NCc)   /* 64 */

// ---------------- scratch (no mallocs allowed) ----------------
__device__ float g_h[BGc*Dc];
__device__ float g_z[BGc*Dc];
__device__ float g_q[BGc*Dc];
__device__ float g_k[BGc*Dc];
__device__ float g_v[BGc*Dc];
__device__ float g_u[BGc*FFNc];
__device__ float g_cKV[Bc*Hc*NCc*HDc*HDc];
__device__ float g_cK[Bc*Hc*NCc*HDc];

// ---------------- embed ----------------
__global__ void embed_kernel(const float* __restrict__ x, const float* __restrict__ ge){
    int row = blockIdx.x;
    int d = threadIdx.x;
    int g = row % Gc;
    float xv = x[row];
    int i = (d < Dc/2) ? d : d - Dc/2;
    float invf = expf(-((2.0f*(float)i)/(float)Dc) * 4.6051701859880914f);
    float f = xv * invf;
    float ree = (d < Dc/2) ? sinf(f) : cosf(f);
    if (xv == -10.0f) ree = 0.0f;
    g_h[(size_t)row*Dc + d] = ge[(size_t)g*Dc + d] + ree;
}

// ---------------- layernorm: warp-per-row ----------------
__global__ void ln_kernel(const float* __restrict__ in, const float* __restrict__ gamma,
                          const float* __restrict__ beta, float* __restrict__ out){
    int row  = blockIdx.x*8 + (threadIdx.x >> 5);
    int lane = threadIdx.x & 31;
    const float* p = in + (size_t)row*Dc;
    float vals[8]; float s = 0.f;
    #pragma unroll
    for (int j=0;j<8;j++){ vals[j] = p[lane + j*32]; s += vals[j]; }
    #pragma unroll
    for (int o=16;o;o>>=1) s += __shfl_xor_sync(0xffffffffu, s, o);
    float mu = s * (1.0f/(float)Dc);
    float vs = 0.f;
    #pragma unroll
    for (int j=0;j<8;j++){ float dd = vals[j]-mu; vs += dd*dd; }
    #pragma unroll
    for (int o=16;o;o>>=1) vs += __shfl_xor_sync(0xffffffffu, vs, o);
    float r = rsqrtf(vs*(1.0f/(float)Dc) + 1e-5f);
    float* po = out + (size_t)row*Dc;
    #pragma unroll
    for (int j=0;j<8;j++){
        int c = lane + j*32;
        po[c] = (vals[j]-mu)*r*gamma[c] + beta[c];
    }
}

// ---------------- bf16 split-precision tensor-core GEMM (R2 structure) ----------------
#define EPI_NONE   0
#define EPI_SQUARE 1
#define EPI_GELU   2

__device__ __forceinline__ uint16_t bfb(float x){
    __nv_bfloat16 h = __float2bfloat16(x);
    return *reinterpret_cast<uint16_t*>(&h);
}
__device__ __forceinline__ float bff(uint16_t b){
    __nv_bfloat16 h = *reinterpret_cast<__nv_bfloat16*>(&b);
    return __bfloat162float(h);
}
__device__ __forceinline__ uint32_t pack2(uint16_t lo, uint16_t hi){
    return ((uint32_t)hi<<16) | (uint32_t)lo;
}
__device__ __forceinline__ void mma16816(float* c, const uint32_t* a, const uint32_t* b){
    asm volatile("mma.sync.aligned.m16n8k16.row.col.f32.bf16.bf16.f32 "
        "{%0,%1,%2,%3}, {%4,%5,%6,%7}, {%8,%9}, {%0,%1,%2,%3};\n"
        : "+f"(c[0]),"+f"(c[1]),"+f"(c[2]),"+f"(c[3])
        : "r"(a[0]),"r"(a[1]),"r"(a[2]),"r"(a[3]), "r"(b[0]),"r"(b[1]));
}

#define ASTR 40
#define BSTR 136

template<int EPI, bool RES, bool QKV>
__global__ void __launch_bounds__(256,1) mma_gemm(int M, int N, int K,
        const float* __restrict__ A,
        const float* W0, const float* W1, const float* W2,
        const float* b0, const float* b1, const float* b2,
        float* C0, float* C1, float* C2){
    __shared__ uint16_t Ah[128*ASTR];
    __shared__ uint16_t Al[128*ASTR];
    __shared__ uint32_t Bh[16*BSTR];
    __shared__ uint32_t Bl[16*BSTR];

    const int z = QKV ? blockIdx.z : 0;
    const float* Bw   = (z==0)?W0:((z==1)?W1:W2);
    const float* bias = (z==0)?b0:((z==1)?b1:b2);
    float*       C    = (z==0)?C0:((z==1)?C1:C2);

    const int tid  = threadIdx.x;
    const int row0 = blockIdx.y*128;
    const int col0 = blockIdx.x*128;
    const int w    = tid>>5;
    const int wm   = w & 3;
    const int wn   = w >> 2;
    const int lane = tid & 31;
    const int g    = lane >> 2;
    const int t4   = lane & 3;

    float a_pre[16];
    float b_pre[16];

    {
        #pragma unroll
        for (int i=0;i<4;i++){
            int id = tid + i*256;
            int r = id>>3, c = (id&7)*4;
            const float4 v = *(const float4*)(A + (size_t)(row0+r)*K + c);
            a_pre[i*4+0]=v.x; a_pre[i*4+1]=v.y; a_pre[i*4+2]=v.z; a_pre[i*4+3]=v.w;
        }
        #pragma unroll
        for (int i=0;i<8;i++){
            int id = tid + i*256;
            int k2 = id>>7, n = id&127;
            const float* p = Bw + (size_t)(2*k2)*N + col0 + n;
            b_pre[2*i+0] = p[0];
            b_pre[2*i+1] = p[N];
        }
    }

    float acc[2][8][4];
    #pragma unroll
    for (int mt=0;mt<2;mt++)
        #pragma unroll
        for (int nt=0;nt<8;nt++)
            #pragma unroll
            for (int q=0;q<4;q++) acc[mt][nt][q]=0.f;

    const int nk = K/32;
    for (int kt=0; kt<nk; kt++){
        #pragma unroll
        for (int i=0;i<4;i++){
            int id = tid + i*256;
            int r = id>>3, c = (id&7)*4;
            uint16_t h[4], l[4];
            #pragma unroll
            for (int j=0;j<4;j++){
                float v = a_pre[i*4+j];
                h[j] = bfb(v);
                l[j] = bfb(v - bff(h[j]));
            }
            *(uint32_t*)&Ah[r*ASTR+c]   = pack2(h[0],h[1]);
            *(uint32_t*)&Ah[r*ASTR+c+2] = pack2(h[2],h[3]);
            *(uint32_t*)&Al[r*ASTR+c]   = pack2(l[0],l[1]);
            *(uint32_t*)&Al[r*ASTR+c+2] = pack2(l[2],l[3]);
        }
        #pragma unroll
        for (int i=0;i<8;i++){
            int id = tid + i*256;
            int k2 = id>>7, n = id&127;
            float v0 = b_pre[2*i+0], v1 = b_pre[2*i+1];
            uint16_t h0 = bfb(v0), h1 = bfb(v1);
            uint16_t l0 = bfb(v0 - bff(h0)), l1 = bfb(v1 - bff(h1));
            Bh[k2*BSTR+n] = pack2(h0,h1);
            Bl[k2*BSTR+n] = pack2(l0,l1);
        }
        __syncthreads();

        if (kt+1 < nk){
            int k0 = (kt+1)*32;
            #pragma unroll
            for (int i=0;i<4;i++){
                int id = tid + i*256;
                int r = id>>3, c = (id&7)*4;
                const float4 v = *(const float4*)(A + (size_t)(row0+r)*K + k0 + c);
                a_pre[i*4+0]=v.x; a_pre[i*4+1]=v.y; a_pre[i*4+2]=v.z; a_pre[i*4+3]=v.w;
            }
            #pragma unroll
            for (int i=0;i<8;i++){
                int id = tid + i*256;
                int k2 = id>>7, n = id&127;
                const float* p = Bw + (size_t)(k0+2*k2)*N + col0 + n;
                b_pre[2*i+0] = p[0];
                b_pre[2*i+1] = p[N];
            }
        }

        #pragma unroll
        for (int ks=0;ks<2;ks++){
            uint32_t afh[2][4], afl[2][4];
            #pragma unroll
            for (int mt=0;mt<2;mt++){
                int r  = wm*32 + mt*16 + g;
                int cb = ks*16 + t4*2;
                afh[mt][0]=*(const uint32_t*)&Ah[r*ASTR+cb];
                afh[mt][1]=*(const uint32_t*)&Ah[(r+8)*ASTR+cb];
                afh[mt][2]=*(const uint32_t*)&Ah[r*ASTR+cb+8];
                afh[mt][3]=*(const uint32_t*)&Ah[(r+8)*ASTR+cb+8];
                afl[mt][0]=*(const uint32_t*)&Al[r*ASTR+cb];
                afl[mt][1]=*(const uint32_t*)&Al[(r+8)*ASTR+cb];
                afl[mt][2]=*(const uint32_t*)&Al[r*ASTR+cb+8];
                afl[mt][3]=*(const uint32_t*)&Al[(r+8)*ASTR+cb+8];
            }
            #pragma unroll
            for (int nt=0;nt<8;nt++){
                int n  = wn*64 + nt*8 + g;
                int k2 = ks*8 + t4;
                uint32_t bhv[2], blv[2];
                bhv[0]=Bh[k2*BSTR+n]; bhv[1]=Bh[(k2+4)*BSTR+n];
                blv[0]=Bl[k2*BSTR+n]; blv[1]=Bl[(k2+4)*BSTR+n];
                #pragma unroll
                for (int mt=0;mt<2;mt++){
                    mma16816(acc[mt][nt], afh[mt], bhv);
                    mma16816(acc[mt][nt], afh[mt], blv);
                    mma16816(acc[mt][nt], afl[mt], bhv);
                }
            }
        }
        __syncthreads();
    }

    const int epi = QKV ? ((z==2) ? EPI_NONE : EPI_SQUARE) : EPI;
    #pragma unroll
    for (int mt=0;mt<2;mt++){
        #pragma unroll
        for (int nt=0;nt<8;nt++){
            int r = row0 + wm*32 + mt*16 + g;
            int n = col0 + wn*64 + nt*8 + t4*2;
            #pragma unroll
            for (int half=0; half<2; half++){
                int rr = r + half*8;
                float v0 = acc[mt][nt][half*2+0] + bias[n];
                float v1 = acc[mt][nt][half*2+1] + bias[n+1];
                if (epi == EPI_SQUARE){ v0=v0*v0; v1=v1*v1; }
                if (epi == EPI_GELU){
                    v0 = 0.5f*v0*(1.0f + erff(v0*0.70710678118654752f));
                    v1 = 0.5f*v1*(1.0f + erff(v1*0.70710678118654752f));
                }
                size_t idx = (size_t)rr*N + n;
                if (RES){ C[idx] += v0; C[idx+1] += v1; }
                else    { C[idx]  = v0; C[idx+1]  = v1; }
            }
        }
    }
}

// ---------------- attention scan ----------------
// A: per-chunk sums of k (x) v, and of k
__global__ void scanA_kernel(){
    int bid = blockIdx.x;
    int c  = bid & (NCc-1);
    int bh = bid >> 5;
    int b  = bh >> 3;
    int hh = bh & 7;
    int m = threadIdx.x & 31;
    int d = threadIdx.x >> 5;
    size_t base = ((size_t)(b*Gc + c*Tc))*Dc + hh*HDc;
    float S = 0.f, ks = 0.f;
    for (int s=0;s<Tc;s++){
        float km = g_k[base + (size_t)s*Dc + m];
        float vd = g_v[base + (size_t)s*Dc + d];
        S  += km*vd;
        ks += km;
    }
    g_cKV[(size_t)bid*1024 + threadIdx.x] = S;     // [bh][c][d][m]
    if (d == 0) g_cK[bid*32 + m] = ks;
}

// B: exclusive prefix over chunks (parallel over bh x 8 segments)
__global__ void scanB_kernel(){
    int bh  = blockIdx.x >> 3;
    int seg = blockIdx.x & 7;
    int t   = seg*128 + threadIdx.x;
    float run = 0.f;
    for (int c=0;c<NCc;c++){
        size_t idx = ((size_t)(bh*NCc + c))*1024 + t;
        float val = g_cKV[idx];
        g_cKV[idx] = run;
        run += val;
    }
    if (seg == 0 && threadIdx.x < 32){
        float run2 = 0.f;
        int m = threadIdx.x;
        for (int c=0;c<NCc;c++){
            int idx = (bh*NCc + c)*32 + m;
            float val = g_cK[idx];
            g_cK[idx] = run2;
            run2 += val;
        }
    }
}

// C: tile-matmul form. P = Q K^T (tril inclusive), num = P V + Q KVpre, den = rowsum(P) + q.kpre
__global__ void __launch_bounds__(256) scanC_kernel(){
    __shared__ float Qs[Tc][33];
    __shared__ float Ks[Tc][33];
    __shared__ float Vs[Tc][33];
    __shared__ float Ps[Tc][65];
    __shared__ float KVsm[32*33];   // [m][d] transposed
    __shared__ float kps[32];
    __shared__ float dens[Tc];

    int bid = blockIdx.x;
    int c  = bid & (NCc-1);
    int bh = bid >> 5;
    int b  = bh >> 3;
    int hh = bh & 7;
    int tid = threadIdx.x;
    size_t base = ((size_t)(b*Gc + c*Tc))*Dc + hh*HDc;

    // load q,k,v chunk tiles
    #pragma unroll
    for (int i=0;i<8;i++){
        int idx = tid + i*256;           // 0..2047
        int s = idx >> 5, m = idx & 31;
        size_t gi = base + (size_t)s*Dc + m;
        Qs[s][m] = g_q[gi];
        Ks[s][m] = g_k[gi];
        Vs[s][m] = g_v[gi];
    }
    // load chunk-prefix KV (transpose to [m][d]) and kpre
    #pragma unroll
    for (int i=0;i<4;i++){
        int idx = tid + i*256;           // 0..1023, layout [d][m]
        int d = idx >> 5, m = idx & 31;
        KVsm[m*33 + d] = g_cKV[(size_t)bid*1024 + idx];
    }
    if (tid < 32) kps[tid] = g_cK[bid*32 + tid];
    __syncthreads();

    // P phase: thread (s = tid>>2, quad = tid&3) computes 16 t-values
    {
        int s = tid >> 2;
        int quad = tid & 3;
        float qreg[32];
        #pragma unroll
        for (int m=0;m<32;m++) qreg[m] = Qs[s][m];
        float rowsum = 0.f;
        #pragma unroll
        for (int j=0;j<16;j++){
            int t = quad + j*4;
            float dot = 0.f;
            #pragma unroll
            for (int m=0;m<32;m++) dot += qreg[m]*Ks[t][m];
            float pv = (t <= s) ? dot : 0.f;
            Ps[s][t] = pv;
            rowsum += pv;
        }
        rowsum += __shfl_xor_sync(0xffffffffu, rowsum, 1);
        rowsum += __shfl_xor_sync(0xffffffffu, rowsum, 2);
        if (quad == 0) dens[s] = rowsum;
    }
    __syncthreads();
    if (tid < Tc){
        float den = dens[tid];
        #pragma unroll
        for (int m=0;m<32;m++) den += Qs[tid][m]*kps[m];
        dens[tid] = den + 1e-16f;
    }
    __syncthreads();

    // output phase: 2048 outputs / 256 threads
    #pragma unroll
    for (int i=0;i<8;i++){
        int idx = tid + i*256;
        int s = idx >> 5, d = idx & 31;
        float num = 0.f;
        #pragma unroll
        for (int t=0;t<Tc;t++) num += Ps[s][t]*Vs[t][d];
        #pragma unroll
        for (int m=0;m<32;m++) num += Qs[s][m]*KVsm[m*33 + d];
        g_h[base + (size_t)s*Dc + d] += num / dens[s];
    }
}

// ---------------- head ----------------
__global__ void out_kernel(const float* __restrict__ Wo, const float* __restrict__ bo,
                           float* __restrict__ out){
    int row  = blockIdx.x*8 + (threadIdx.x >> 5);
    int lane = threadIdx.x & 31;
    float s = 0.f;
    #pragma unroll
    for (int j=0;j<8;j++){
        int d = lane + j*32;
        s += g_h[(size_t)row*Dc + d] * Wo[d];
    }
    #pragma unroll
    for (int o=16;o;o>>=1) s += __shfl_xor_sync(0xffffffffu, s, o);
    if (lane == 0) out[row] = s + bo[0];
}

// ---------------- launch ----------------
extern "C" void kernel_launch(void* const* d_in, const int* in_sizes, int n_in,
                              void* d_out, int out_size){
    const float* x    = (const float*)d_in[0];
    const float* ge   = (const float*)d_in[1];
    const float* Wq   = (const float*)d_in[2];
    const float* bq   = (const float*)d_in[3];
    const float* Wk   = (const float*)d_in[4];
    const float* bk   = (const float*)d_in[5];
    const float* Wv   = (const float*)d_in[6];
    const float* bv   = (const float*)d_in[7];
    const float* ln1g = (const float*)d_in[8];
    const float* ln1b = (const float*)d_in[9];
    const float* ln2g = (const float*)d_in[10];
    const float* ln2b = (const float*)d_in[11];
    const float* WU   = (const float*)d_in[12];
    const float* bU   = (const float*)d_in[13];
    const float* WV   = (const float*)d_in[14];
    const float* bV   = (const float*)d_in[15];
    const float* Wo   = (const float*)d_in[16];
    const float* bo   = (const float*)d_in[17];
    float* out = (float*)d_out;

    float *ph, *pz, *pq, *pk, *pv, *pu;
    cudaGetSymbolAddress((void**)&ph, g_h);
    cudaGetSymbolAddress((void**)&pz, g_z);
    cudaGetSymbolAddress((void**)&pq, g_q);
    cudaGetSymbolAddress((void**)&pk, g_k);
    cudaGetSymbolAddress((void**)&pv, g_v);
    cudaGetSymbolAddress((void**)&pu, g_u);

    embed_kernel<<<BGc, Dc>>>(x, ge);

    for (int l=0;l<Lc;l++){
        ln_kernel<<<BGc/8, 256>>>(ph, ln1g + l*Dc, ln1b + l*Dc, pz);
        dim3 gqkv(Dc/128, BGc/128, 3);
        mma_gemm<EPI_NONE,false,true><<<gqkv,256>>>(BGc, Dc, Dc, pz,
            Wq + (size_t)l*Dc*Dc, Wk + (size_t)l*Dc*Dc, Wv + (size_t)l*Dc*Dc,
            bq + l*Dc, bk + l*Dc, bv + l*Dc,
            pq, pk, pv);
        scanA_kernel<<<Bc*Hc*NCc, 1024>>>();
        scanB_kernel<<<Bc*Hc*8, 128>>>();
        scanC_kernel<<<Bc*Hc*NCc, 256>>>();

        ln_kernel<<<BGc/8, 256>>>(ph, ln2g + l*Dc, ln2b + l*Dc, pz);
        dim3 gu(FFNc/128, BGc/128, 1);
        mma_gemm<EPI_GELU,false,false><<<gu,256>>>(BGc, FFNc, Dc, pz,
            WU + (size_t)l*Dc*FFNc, 0, 0, bU + l*FFNc, 0, 0, pu, 0, 0);
        dim3 gv(Dc/128, BGc/128, 1);
        mma_gemm<EPI_NONE,true,false><<<gv,256>>>(BGc, Dc, FFNc, pu,
            WV + (size_t)l*FFNc*Dc, 0, 0, bV + l*Dc, 0, 0, ph, 0, 0);
    }

    out_kernel<<<BGc/8, 256>>>(Wo, bo, out);
}